// round 1
// baseline (speedup 1.0000x reference)
#include <cuda_runtime.h>
#include <math.h>

// Problem constants: x [B,T,C] fp32, W_kqv [C, 3C] fp32, out [B,T,C] fp32.
#define BB 4
#define TT 2048
#define CC 1024

// Scratch (static __device__ arrays — no allocation in kernel_launch).
__device__ float g_qkv[(size_t)BB * TT * 3 * CC];   // [B,T,3C]  (q | k | v)  ~96 MB
__device__ float g_S  [(size_t)BB * TT * TT];        // [B,T,T]   scores/probs ~64 MB

// ---------------------------------------------------------------------------
// Tiled fp32 GEMM. BM=BN=128, BK=8, 256 threads, 8x8 micro-tile per thread.
// TRANSB:     C[i,j] = sum_k A[i,k] * B[j,k]   (NT, for Q·K^T)
// CAUSAL_SKIP: skip tiles entirely above the diagonal (bn > bm+127)
// LIMIT_K:    truncate K loop at bm+128 (P rows are zero past the diagonal)
// All dims here are multiples of 128 / K multiples of 8 — no bounds checks.
// ---------------------------------------------------------------------------
template <bool TRANSB, bool CAUSAL_SKIP, bool LIMIT_K>
__global__ void __launch_bounds__(256, 2)
gemm128(const float* __restrict__ A, const float* __restrict__ B,
        float* __restrict__ C,
        int M, int N, int K,
        int lda, int ldb, int ldc,
        long sA, long sB, long sC,
        float scale)
{
    const int bz = blockIdx.z;
    A += (long)bz * sA;
    B += (long)bz * sB;
    C += (long)bz * sC;

    const int bm = blockIdx.y * 128;
    const int bn = blockIdx.x * 128;

    if (CAUSAL_SKIP && bn > bm + 127) return;   // tile fully masked

    int kend = K;
    if (LIMIT_K) kend = min(K, bm + 128);

    __shared__ float As[8][132];   // padded: conflict-free transposed stores + LDS.128 reads
    __shared__ float Bs[8][132];

    const int tid = threadIdx.x;          // 0..255
    const int tx  = tid & 15;             // micro-tile column group
    const int ty  = tid >> 4;             // micro-tile row group

    // A-load mapping (always transposed into As[k][m])
    const int arow = tid >> 1;            // 0..127
    const int akp  = (tid & 1) << 2;      // 0 or 4

    // B-load mappings
    const int bkrow = tid >> 5;           // NN: 0..7
    const int bcol  = (tid & 31) << 2;    // NN: 0..124
    const int brow  = tid >> 1;           // NT: 0..127
    const int bkp   = (tid & 1) << 2;     // NT: 0 or 4

    float acc[8][8];
#pragma unroll
    for (int i = 0; i < 8; i++)
#pragma unroll
        for (int j = 0; j < 8; j++) acc[i][j] = 0.0f;

    for (int k0 = 0; k0 < kend; k0 += 8) {
        const float4 av = *(const float4*)&A[(size_t)(bm + arow) * lda + k0 + akp];
        float4 bv;
        if (TRANSB)
            bv = *(const float4*)&B[(size_t)(bn + brow) * ldb + k0 + bkp];
        else
            bv = *(const float4*)&B[(size_t)(k0 + bkrow) * ldb + bn + bcol];

        __syncthreads();   // previous iteration's reads complete before overwrite

        As[akp + 0][arow] = av.x;
        As[akp + 1][arow] = av.y;
        As[akp + 2][arow] = av.z;
        As[akp + 3][arow] = av.w;
        if (TRANSB) {
            Bs[bkp + 0][brow] = bv.x;
            Bs[bkp + 1][brow] = bv.y;
            Bs[bkp + 2][brow] = bv.z;
            Bs[bkp + 3][brow] = bv.w;
        } else {
            *(float4*)&Bs[bkrow][bcol] = bv;
        }
        __syncthreads();

#pragma unroll
        for (int k = 0; k < 8; k++) {
            float a[8], b[8];
            *(float4*)&a[0] = *(const float4*)&As[k][ty * 8];
            *(float4*)&a[4] = *(const float4*)&As[k][ty * 8 + 4];
            *(float4*)&b[0] = *(const float4*)&Bs[k][tx * 8];
            *(float4*)&b[4] = *(const float4*)&Bs[k][tx * 8 + 4];
#pragma unroll
            for (int i = 0; i < 8; i++)
#pragma unroll
                for (int j = 0; j < 8; j++)
                    acc[i][j] = fmaf(a[i], b[j], acc[i][j]);
        }
    }

    // Epilogue (scaled), float4 stores
#pragma unroll
    for (int i = 0; i < 8; i++) {
        float* crow = &C[(size_t)(bm + ty * 8 + i) * ldc + bn + tx * 8];
        float4 v0, v1;
        v0.x = acc[i][0] * scale; v0.y = acc[i][1] * scale;
        v0.z = acc[i][2] * scale; v0.w = acc[i][3] * scale;
        v1.x = acc[i][4] * scale; v1.y = acc[i][5] * scale;
        v1.z = acc[i][6] * scale; v1.w = acc[i][7] * scale;
        *(float4*)&crow[0] = v0;
        *(float4*)&crow[4] = v1;
    }
}

// ---------------------------------------------------------------------------
// Causal row softmax, in place on S. One block (256 thr) per row.
// Row i of batch b: softmax over [0, i]; entries (i, TT) set to 0 so the
// P·V GEMM never reads garbage from skipped score tiles.
// ---------------------------------------------------------------------------
__global__ void softmax_causal(float* __restrict__ S)
{
    const int row = blockIdx.x;            // 0 .. B*T-1
    const int b   = row / TT;
    const int i   = row % TT;
    float* Srow = S + (size_t)b * TT * TT + (size_t)i * TT;
    const int len = i + 1;
    const int t = threadIdx.x;

    __shared__ float sh[8];

    // ---- max ----
    float mx = -INFINITY;
    for (int j = t; j < len; j += 256) mx = fmaxf(mx, Srow[j]);
#pragma unroll
    for (int o = 16; o; o >>= 1) mx = fmaxf(mx, __shfl_xor_sync(0xffffffffu, mx, o));
    if ((t & 31) == 0) sh[t >> 5] = mx;
    __syncthreads();
    mx = sh[0];
#pragma unroll
    for (int w = 1; w < 8; w++) mx = fmaxf(mx, sh[w]);
    __syncthreads();   // sh reuse guard

    // ---- exp + sum (exp written in place) ----
    float sum = 0.0f;
    for (int j = t; j < len; j += 256) {
        float e = __expf(Srow[j] - mx);
        Srow[j] = e;
        sum += e;
    }
#pragma unroll
    for (int o = 16; o; o >>= 1) sum += __shfl_xor_sync(0xffffffffu, sum, o);
    if ((t & 31) == 0) sh[t >> 5] = sum;
    __syncthreads();
    sum = sh[0];
#pragma unroll
    for (int w = 1; w < 8; w++) sum += sh[w];

    const float inv = 1.0f / sum;
    for (int j = t; j < len; j += 256) Srow[j] *= inv;
    for (int j = len + t; j < TT; j += 256) Srow[j] = 0.0f;   // zero masked tail
}

// ---------------------------------------------------------------------------
extern "C" void kernel_launch(void* const* d_in, const int* in_sizes, int n_in,
                              void* d_out, int out_size)
{
    const float* x = (const float*)d_in[0];       // [B,T,C]
    const float* W = (const float*)d_in[1];       // [C,3C]
    float* out = (float*)d_out;                   // [B,T,C]

    float *qkv, *S;
    cudaGetSymbolAddress((void**)&qkv, g_qkv);
    cudaGetSymbolAddress((void**)&S,   g_S);

    const dim3 blk(256);

    // 1) qkv = x @ W_kqv : [8192,1024] x [1024,3072]
    gemm128<false, false, false><<<dim3(3 * CC / 128, BB * TT / 128, 1), blk>>>(
        x, W, qkv,
        BB * TT, 3 * CC, CC,
        CC, 3 * CC, 3 * CC,
        0, 0, 0, 1.0f);

    // 2) S = Q K^T / sqrt(C), per batch (NT, causal tile-skip)
    gemm128<true, true, false><<<dim3(TT / 128, TT / 128, BB), blk>>>(
        qkv, qkv + CC, S,
        TT, TT, CC,
        3 * CC, 3 * CC, TT,
        (long)TT * 3 * CC, (long)TT * 3 * CC, (long)TT * TT,
        0.03125f /* 1/sqrt(1024) */);

    // 3) causal softmax in place
    softmax_causal<<<BB * TT, 256>>>(S);

    // 4) Y = P @ V, per batch (NN, K-loop truncated past diagonal)
    gemm128<false, false, true><<<dim3(CC / 128, TT / 128, BB), blk>>>(
        S, qkv + 2 * CC, out,
        TT, CC, TT,
        TT, 3 * CC, CC,
        (long)TT * TT, (long)TT * 3 * CC, (long)TT * CC,
        1.0f);
}

// round 3
// speedup vs baseline: 5.7111x; 5.7111x over previous
#include <cuda_runtime.h>
#include <cuda_fp16.h>
#include <math.h>
#include <stdint.h>

#define BB 4
#define TT 2048
#define CC 1024

// ---- scratch (static device globals; no allocs anywhere) --------------------
__device__ __align__(256) __half g_xh  [(size_t)BB * TT * CC];        // x in half
__device__ __align__(256) __half g_Wth [(size_t)3 * CC * CC];         // W^T [3C,C] half
__device__ __align__(256) __half g_qkvh[(size_t)BB * TT * 3 * CC];    // [B,T,3C] half
__device__ __align__(256) __half g_Vth [(size_t)BB * CC * TT];        // [B,C,T] half
__device__ __align__(256) float  g_S   [(size_t)BB * TT * TT];        // scores fp32
__device__ __align__(256) __half g_Ph  [(size_t)BB * TT * TT];        // probs half

// ---- helpers ------------------------------------------------------------------
__device__ __forceinline__ uint32_t smem_u32(const void* p) {
    uint32_t a;
    asm("{ .reg .u64 t; cvta.to.shared.u64 t, %1; cvt.u32.u64 %0, t; }"
        : "=r"(a) : "l"(p));
    return a;
}
__device__ __forceinline__ void cp16(uint32_t dst, const void* src) {
    asm volatile("cp.async.cg.shared.global [%0], [%1], 16;"
                 :: "r"(dst), "l"(src) : "memory");
}
#define CP_COMMIT() asm volatile("cp.async.commit_group;" ::: "memory")
#define CP_WAIT(n)  asm volatile("cp.async.wait_group %0;" :: "n"(n) : "memory")

#define LDSM4(r, addr)                                                          \
    asm volatile("ldmatrix.sync.aligned.m8n8.x4.shared.b16 {%0,%1,%2,%3},[%4];" \
        : "=r"((r)[0]), "=r"((r)[1]), "=r"((r)[2]), "=r"((r)[3])                \
        : "r"(addr))

#define MMA16816(c, a, b0, b1)                                                  \
    asm volatile("mma.sync.aligned.m16n8k16.row.col.f32.f16.f16.f32 "           \
        "{%0,%1,%2,%3},{%4,%5,%6,%7},{%8,%9},{%0,%1,%2,%3};"                    \
        : "+f"((c)[0]), "+f"((c)[1]), "+f"((c)[2]), "+f"((c)[3])                 \
        : "r"((a)[0]), "r"((a)[1]), "r"((a)[2]), "r"((a)[3]),                    \
          "r"(b0), "r"(b1))

// ---- fp16 HMMA GEMM: C[M,N] = scale * A[M,K] * B[N,K]^T (A,B half, row-major)
// 128x128 tile, BK=32, 4-stage cp.async, 256 thr (8 warps, 2x4 of 64x32).
#define STAGES     4
#define ASTRIDE    80                 // bytes per smem row (64B data + 16B pad)
#define AT_BYTES   (128 * ASTRIDE)    // 10240
#define STG_BYTES  (2 * AT_BYTES)     // 20480
#define SMEM_TOTAL (STAGES * STG_BYTES)

template <bool CSKIP, bool LIMK, bool OUTH>
__global__ void __launch_bounds__(256, 2)
gemm_hmma(const __half* __restrict__ A, const __half* __restrict__ B,
          void* __restrict__ Cout,
          int K, int lda, int ldb, int ldc,
          long sA, long sB, long sC, float scale)
{
    extern __shared__ char smem[];
    const int bz = blockIdx.z;
    A += (long)bz * sA;
    B += (long)bz * sB;

    const int bm = blockIdx.y * 128;
    const int bn = blockIdx.x * 128;
    if (CSKIP && bn > bm + 127) return;                 // fully masked tile
    const int kend = LIMK ? min(K, bm + 128) : K;
    const int nch  = kend >> 5;                         // 32-K chunks

    const int tid = threadIdx.x, lane = tid & 31, wid = tid >> 5;
    const int m0 = (wid >> 2) * 64, n0 = (wid & 3) * 32;
    const uint32_t sb = smem_u32(smem);

    const int arow = tid >> 2;          // loader: chunk row for idx=tid
    const int ac   = tid & 3;           // chunk column (16B units)

    float acc[4][4][4];
#pragma unroll
    for (int i = 0; i < 4; i++)
#pragma unroll
        for (int j = 0; j < 4; j++)
#pragma unroll
            for (int q = 0; q < 4; q++) acc[i][j][q] = 0.0f;

#define LOAD_STAGE(kt, s)                                                        \
    do {                                                                         \
        const __half* Ab_ = A + (size_t)bm * lda + (kt) * 32;                    \
        const __half* Bb_ = B + (size_t)bn * ldb + (kt) * 32;                    \
        const uint32_t sa_ = sb + (s) * STG_BYTES;                               \
        const uint32_t sbb_ = sa_ + AT_BYTES;                                    \
        _Pragma("unroll")                                                        \
        for (int i_ = 0; i_ < 2; i_++) {                                         \
            const int r_ = arow + i_ * 64;                                       \
            cp16(sa_  + r_ * ASTRIDE + ac * 16, Ab_ + (size_t)r_ * lda + ac * 8);\
            cp16(sbb_ + r_ * ASTRIDE + ac * 16, Bb_ + (size_t)r_ * ldb + ac * 8);\
        }                                                                        \
    } while (0)

    // prologue
#pragma unroll
    for (int s = 0; s < STAGES - 1; s++) {
        if (s < nch) LOAD_STAGE(s, s);
        CP_COMMIT();
    }

    for (int kt = 0; kt < nch; kt++) {
        CP_WAIT(STAGES - 2);
        __syncthreads();

        const int s = kt & (STAGES - 1);
        const uint32_t sa  = sb + s * STG_BYTES;
        const uint32_t sbb = sa + AT_BYTES;
#pragma unroll
        for (int ks = 0; ks < 2; ks++) {                // two k16 steps
            uint32_t a[4][4], b[2][4];
#pragma unroll
            for (int mf = 0; mf < 4; mf++) {
                const uint32_t addr = sa
                    + (m0 + mf * 16 + (lane & 15)) * ASTRIDE
                    + ks * 32 + ((lane >> 4) & 1) * 16;
                LDSM4(a[mf], addr);
            }
#pragma unroll
            for (int nb = 0; nb < 2; nb++) {
                const uint32_t addr = sbb
                    + (n0 + nb * 16 + ((lane >> 4) & 1) * 8 + (lane & 7)) * ASTRIDE
                    + ks * 32 + ((lane >> 3) & 1) * 16;
                LDSM4(b[nb], addr);
            }
#pragma unroll
            for (int mf = 0; mf < 4; mf++)
#pragma unroll
                for (int nf = 0; nf < 4; nf++)
                    MMA16816(acc[mf][nf], a[mf],
                             b[nf >> 1][(nf & 1) * 2],
                             b[nf >> 1][(nf & 1) * 2 + 1]);
        }
        __syncthreads();

        const int nk = kt + STAGES - 1;
        if (nk < nch) LOAD_STAGE(nk, nk & (STAGES - 1));
        CP_COMMIT();
    }

    // epilogue
    const int gr = lane >> 2, gc = (lane & 3) * 2;
#pragma unroll
    for (int mf = 0; mf < 4; mf++) {
        const int row = bm + m0 + mf * 16 + gr;
#pragma unroll
        for (int nf = 0; nf < 4; nf++) {
            const int col = bn + n0 + nf * 8 + gc;
            const float v0 = acc[mf][nf][0] * scale;
            const float v1 = acc[mf][nf][1] * scale;
            const float v2 = acc[mf][nf][2] * scale;
            const float v3 = acc[mf][nf][3] * scale;
            if (OUTH) {
                __half* Cp = (__half*)Cout + (long)bz * sC;
                *(__half2*)(Cp + (size_t)row * ldc + col) =
                    __floats2half2_rn(v0, v1);
                *(__half2*)(Cp + (size_t)(row + 8) * ldc + col) =
                    __floats2half2_rn(v2, v3);
            } else {
                float* Cp = (float*)Cout + (long)bz * sC;
                *(float2*)(Cp + (size_t)row * ldc + col) = make_float2(v0, v1);
                *(float2*)(Cp + (size_t)(row + 8) * ldc + col) = make_float2(v2, v3);
            }
        }
    }
#undef LOAD_STAGE
}

// ---- fp32 -> fp16 copy ---------------------------------------------------------
__global__ void cvt_half(const float* __restrict__ x, __half* __restrict__ xh, int n2)
{
    int i = blockIdx.x * blockDim.x + threadIdx.x;
    for (; i < n2; i += gridDim.x * blockDim.x) {
        float2 v = ((const float2*)x)[i];
        ((__half2*)xh)[i] = __floats2half2_rn(v.x, v.y);
    }
}

// ---- W^T (fp32 in, half out) ----------------------------------------------------
__global__ void transposeW(const float* __restrict__ W, __half* __restrict__ Wt)
{
    __shared__ float t[32][33];
    const int d0 = blockIdx.x * 32, c0 = blockIdx.y * 32;
    const int x = threadIdx.x, y = threadIdx.y;
#pragma unroll
    for (int i = 0; i < 32; i += 8)
        t[y + i][x] = W[(size_t)(c0 + y + i) * (3 * CC) + d0 + x];
    __syncthreads();
#pragma unroll
    for (int i = 0; i < 32; i += 8)
        Wt[(size_t)(d0 + y + i) * CC + c0 + x] = __float2half_rn(t[x][y + i]);
}

// ---- V^T (half in, half out), per batch ------------------------------------------
__global__ void transposeV(const __half* __restrict__ qkv, __half* __restrict__ Vt)
{
    __shared__ __half t[32][34];
    const int b = blockIdx.z;
    const int t0 = blockIdx.x * 32, c0 = blockIdx.y * 32;
    const int x = threadIdx.x, y = threadIdx.y;
    const __half* src = qkv + (size_t)b * TT * 3 * CC + 2 * CC;
#pragma unroll
    for (int i = 0; i < 32; i += 8)
        t[y + i][x] = src[(size_t)(t0 + y + i) * (3 * CC) + c0 + x];
    __syncthreads();
    __half* dst = Vt + (size_t)b * CC * TT;
#pragma unroll
    for (int i = 0; i < 32; i += 8)
        dst[(size_t)(c0 + y + i) * TT + t0 + x] = t[x][y + i];
}

// ---- causal softmax: S fp32 in (in-place exp), P half out -------------------------
__global__ void softmax_causal(float* __restrict__ S, __half* __restrict__ P)
{
    const int row = blockIdx.x;
    const int b = row / TT;
    const int i = row % TT;
    float* Srow = S + (size_t)b * TT * TT + (size_t)i * TT;
    __half* Prow = P + (size_t)b * TT * TT + (size_t)i * TT;
    const int len = i + 1;
    const int t = threadIdx.x;

    __shared__ float sh[8];

    float mx = -INFINITY;
    for (int j = t; j < len; j += 256) mx = fmaxf(mx, Srow[j]);
#pragma unroll
    for (int o = 16; o; o >>= 1) mx = fmaxf(mx, __shfl_xor_sync(0xffffffffu, mx, o));
    if ((t & 31) == 0) sh[t >> 5] = mx;
    __syncthreads();
    mx = sh[0];
#pragma unroll
    for (int w = 1; w < 8; w++) mx = fmaxf(mx, sh[w]);
    __syncthreads();

    float sum = 0.0f;
    for (int j = t; j < len; j += 256) {
        float e = __expf(Srow[j] - mx);
        Srow[j] = e;
        sum += e;
    }
#pragma unroll
    for (int o = 16; o; o >>= 1) sum += __shfl_xor_sync(0xffffffffu, sum, o);
    if ((t & 31) == 0) sh[t >> 5] = sum;
    __syncthreads();
    sum = sh[0];
#pragma unroll
    for (int w = 1; w < 8; w++) sum += sh[w];

    const float inv = 1.0f / sum;
    for (int j = t; j < len; j += 256) Prow[j] = __float2half_rn(Srow[j] * inv);
    const __half hz = __float2half_rn(0.0f);
    for (int j = len + t; j < TT; j += 256) Prow[j] = hz;
}

// ---- launch -----------------------------------------------------------------------
extern "C" void kernel_launch(void* const* d_in, const int* in_sizes, int n_in,
                              void* d_out, int out_size)
{
    const float* x = (const float*)d_in[0];   // [B,T,C]
    const float* W = (const float*)d_in[1];   // [C,3C]
    float* out = (float*)d_out;               // [B,T,C]

    __half *xh, *Wth, *qkvh, *Vth, *Ph;
    float *S;
    cudaGetSymbolAddress((void**)&xh,   g_xh);
    cudaGetSymbolAddress((void**)&Wth,  g_Wth);
    cudaGetSymbolAddress((void**)&qkvh, g_qkvh);
    cudaGetSymbolAddress((void**)&Vth,  g_Vth);
    cudaGetSymbolAddress((void**)&S,    g_S);
    cudaGetSymbolAddress((void**)&Ph,   g_Ph);

    cudaFuncSetAttribute(gemm_hmma<false, false, true>,
                         cudaFuncAttributeMaxDynamicSharedMemorySize, SMEM_TOTAL);
    cudaFuncSetAttribute(gemm_hmma<true, false, false>,
                         cudaFuncAttributeMaxDynamicSharedMemorySize, SMEM_TOTAL);
    cudaFuncSetAttribute(gemm_hmma<false, true, false>,
                         cudaFuncAttributeMaxDynamicSharedMemorySize, SMEM_TOTAL);

    // 0a) x -> half
    cvt_half<<<1024, 256>>>(x, xh, BB * TT * CC / 2);
    // 0b) W^T (half)
    transposeW<<<dim3(3 * CC / 32, CC / 32), dim3(32, 8)>>>(W, Wth);

    // 1) qkvh = xh @ Wth^T   [8192,3072] half out
    gemm_hmma<false, false, true><<<dim3(3 * CC / 128, BB * TT / 128, 1), 256, SMEM_TOTAL>>>(
        xh, Wth, qkvh, CC, CC, CC, 3 * CC, 0, 0, 0, 1.0f);

    // 1b) Vth = V^T per batch [C,T]
    transposeV<<<dim3(TT / 32, CC / 32, BB), dim3(32, 8)>>>(qkvh, Vth);

    // 2) S = Q K^T / 32 per batch (fp32 out, causal tile skip)
    gemm_hmma<true, false, false><<<dim3(TT / 128, TT / 128, BB), 256, SMEM_TOTAL>>>(
        qkvh, qkvh + CC, S, CC, 3 * CC, 3 * CC, TT,
        (long)TT * 3 * CC, (long)TT * 3 * CC, (long)TT * TT, 0.03125f);

    // 3) causal softmax -> Ph (half)
    softmax_causal<<<BB * TT, 256>>>(S, Ph);

    // 4) out = Ph @ Vth^T per batch (fp32 out, K truncated at diagonal)
    gemm_hmma<false, true, false><<<dim3(CC / 128, TT / 128, BB), 256, SMEM_TOTAL>>>(
        Ph, Vth, out, TT, TT, TT, CC,
        (long)TT * TT, (long)TT * CC, (long)TT * CC, 1.0f);
}